// round 4
// baseline (speedup 1.0000x reference)
#include <cuda_runtime.h>

// Problem constants
#define P_DIM 64
#define B_DIM 256
#define H_DIM 512
#define IN_DIM 2
#define PB (P_DIM * B_DIM)      // 16384 fused batch rows

// Tiling
#define MT 128                  // rows per CTA
#define HT 32                   // h-columns per CTA (x4 gates -> 128 N cols)
#define KT 32                   // k per pipeline stage
#define PITCH 36                // smem pitch (floats) -> conflict-free frag loads
#define STAGE_F (128 * PITCH)   // floats per (A or B) stage buffer
#define GP 132                  // gate smem pitch

// Layer-0 hidden output scratch (static device global: allocation-free)
__device__ float g_h1[(size_t)PB * H_DIM];

__device__ __forceinline__ unsigned f2tf(float f) {
    unsigned r;
    asm("cvt.rna.tf32.f32 %0, %1;" : "=r"(r) : "f"(f));
    return r;
}

__device__ __forceinline__ void cpa16(unsigned saddr, const float* g) {
    asm volatile("cp.async.cg.shared.global [%0], [%1], 16;\n" :: "r"(saddr), "l"(g));
}

__device__ __forceinline__ void mma_tf32(float* c, const unsigned* a, unsigned b0, unsigned b1) {
    asm volatile(
        "mma.sync.aligned.m16n8k8.row.col.f32.tf32.tf32.f32 "
        "{%0,%1,%2,%3}, {%4,%5,%6,%7}, {%8,%9}, {%0,%1,%2,%3};\n"
        : "+f"(c[0]), "+f"(c[1]), "+f"(c[2]), "+f"(c[3])
        : "r"(a[0]), "r"(a[1]), "r"(a[2]), "r"(a[3]), "r"(b0), "r"(b1));
}

__device__ __forceinline__ float sigmoidf_fast(float x) {
    return 1.0f / (1.0f + __expf(-x));
}

// One LSTM layer, fused GEMM (tf32 mma) + cell.
// LAYER==0: gates = x@w_ih0^T (IN=2, done scalar in epilogue) + h0[:,0]@w_hh0^T + b
// LAYER==1: gates = h1@w_ih1^T + h0[:,1]@w_hh1^T + b  (K=1024 concat)
template <int LAYER>
__global__ void __launch_bounds__(256, 2)
lstm_layer_kernel(const float* __restrict__ x_in,
                  const float* __restrict__ h0,
                  const float* __restrict__ c0,
                  const float* __restrict__ w_ih,
                  const float* __restrict__ w_hh,
                  const float* __restrict__ b_ih,
                  const float* __restrict__ b_hh,
                  float* __restrict__ d_out) {
    extern __shared__ float smem[];

    const int tid  = threadIdx.x;
    const int warp = tid >> 5;
    const int lane = tid & 31;
    const int wm = warp >> 1;          // 0..3 : 32-row slab
    const int wn = warp & 1;           // 0..1 : 64-col half
    const int rowW = wm * 32;
    const int colW = wn * 64;

    const int mTile = blockIdx.y;      // 0..127
    const int hTile = blockIdx.x;      // 0..15
    const int rowBase = mTile * MT;
    const int hBase   = hTile * HT;

    const int p0 = rowBase >> 8;       // row = p*256 + b ; 128-row tile stays in one p
    const int b0 = rowBase & 255;

    // A operand base pointers (rows contiguous with stride H_DIM)
    const float* Ab0;
    const float* Ab1;
    if (LAYER == 0) {
        Ab0 = h0 + ((size_t)(p0 * 2 + 0) * B_DIM + b0) * H_DIM;
        Ab1 = Ab0;  // unused
    } else {
        Ab0 = g_h1 + (size_t)rowBase * H_DIM;
        Ab1 = h0 + ((size_t)(p0 * 2 + 1) * B_DIM + b0) * H_DIM;
    }
    const float* Wb0 = (LAYER == 0) ? w_hh : w_ih;
    const float* Wb1 = w_hh;

    const int KTILES = (LAYER == 0) ? 16 : 32;

    const unsigned smem_u = (unsigned)__cvta_generic_to_shared(smem);

    // -------- stage loader: A tile [128 x KT], B tile [128(gate-blocked n) x KT] --------
    auto load_stage = [&](int kt, int stage) {
        const float* Ab = (LAYER == 0 || kt < 16) ? Ab0 : Ab1;
        const float* Wb = (LAYER == 0 || kt < 16) ? Wb0 : Wb1;
        const int kk = (kt & 15) * KT;
        const unsigned Asd = smem_u + (unsigned)(stage * STAGE_F) * 4u;
        const unsigned Bsd = smem_u + (unsigned)((2 + stage) * STAGE_F) * 4u;
#pragma unroll
        for (int i = 0; i < 4; i++) {
            const int c  = tid + i * 256;       // 0..1023 : 16B chunks
            const int r  = c >> 3;              // 0..127
            const int cc = (c & 7) * 4;         // 0,4,...,28
            cpa16(Asd + (unsigned)(r * PITCH + cc) * 4u,
                  Ab + (size_t)r * H_DIM + kk + cc);
            const int g = r >> 5, j = r & 31;   // gate-blocked weight row
            cpa16(Bsd + (unsigned)(r * PITCH + cc) * 4u,
                  Wb + (size_t)(g * H_DIM + hBase + j) * H_DIM + kk + cc);
        }
        asm volatile("cp.async.commit_group;\n");
    };

    float acc[2][8][4];
#pragma unroll
    for (int mt = 0; mt < 2; mt++)
#pragma unroll
        for (int nt = 0; nt < 8; nt++)
#pragma unroll
            for (int q = 0; q < 4; q++) acc[mt][nt][q] = 0.0f;

    // -------- mainloop: 2-stage cp.async pipeline --------
    load_stage(0, 0);
    for (int kt = 0; kt < KTILES; kt++) {
        if (kt + 1 < KTILES) {
            load_stage(kt + 1, (kt + 1) & 1);
            asm volatile("cp.async.wait_group 1;\n");
        } else {
            asm volatile("cp.async.wait_group 0;\n");
        }
        __syncthreads();

        const float* Asd = smem + (kt & 1) * STAGE_F;
        const float* Bsd = smem + (2 + (kt & 1)) * STAGE_F;
#pragma unroll
        for (int k0 = 0; k0 < KT; k0 += 8) {
            unsigned a[2][4];
            const int ar = rowW + (lane >> 2);
            const int ac = k0 + (lane & 3);
#pragma unroll
            for (int mt = 0; mt < 2; mt++) {
                const float* base = Asd + (ar + mt * 16) * PITCH + ac;
                a[mt][0] = f2tf(base[0]);
                a[mt][1] = f2tf(base[8 * PITCH]);
                a[mt][2] = f2tf(base[4]);
                a[mt][3] = f2tf(base[8 * PITCH + 4]);
            }
#pragma unroll
            for (int nt = 0; nt < 8; nt++) {
                const int bn = colW + nt * 8 + (lane >> 2);
                const float* bb = Bsd + bn * PITCH + k0 + (lane & 3);
                const unsigned bf0 = f2tf(bb[0]);
                const unsigned bf1 = f2tf(bb[4]);
                mma_tf32(acc[0][nt], a[0], bf0, bf1);
                mma_tf32(acc[1][nt], a[1], bf0, bf1);
            }
        }
        __syncthreads();
    }

    // -------- epilogue: gates -> smem (overlay pipeline buffers) --------
    float* G = smem;  // [128][GP], col index = gate*32 + j
#pragma unroll
    for (int mt = 0; mt < 2; mt++) {
#pragma unroll
        for (int nt = 0; nt < 8; nt++) {
            const int r  = rowW + mt * 16 + (lane >> 2);
            const int cC = colW + nt * 8 + 2 * (lane & 3);
            G[r * GP + cC]           = acc[mt][nt][0];
            G[r * GP + cC + 1]       = acc[mt][nt][1];
            G[(r + 8) * GP + cC]     = acc[mt][nt][2];
            G[(r + 8) * GP + cC + 1] = acc[mt][nt][3];
        }
    }
    __syncthreads();

    // -------- LSTM cell + stores --------
    const size_t hn_off = (size_t)PB * H_DIM;                               // out size
    const size_t cn_off = hn_off + (size_t)P_DIM * 2 * B_DIM * H_DIM;       // + hn size

    const int j = tid & 31;           // constant per thread
    const int h = hBase + j;
    // hoist per-thread bias sums and (layer0) input-projection coefficients
    const float bi = b_ih[h]             + b_hh[h];
    const float bf = b_ih[H_DIM + h]     + b_hh[H_DIM + h];
    const float bg = b_ih[2 * H_DIM + h] + b_hh[2 * H_DIM + h];
    const float bo = b_ih[3 * H_DIM + h] + b_hh[3 * H_DIM + h];
    float wi0 = 0.f, wi1 = 0.f, wf0 = 0.f, wf1 = 0.f, wg0 = 0.f, wg1 = 0.f, wo0 = 0.f, wo1 = 0.f;
    if (LAYER == 0) {
        wi0 = w_ih[(size_t)h * 2];                    wi1 = w_ih[(size_t)h * 2 + 1];
        wf0 = w_ih[(size_t)(H_DIM + h) * 2];          wf1 = w_ih[(size_t)(H_DIM + h) * 2 + 1];
        wg0 = w_ih[(size_t)(2 * H_DIM + h) * 2];      wg1 = w_ih[(size_t)(2 * H_DIM + h) * 2 + 1];
        wo0 = w_ih[(size_t)(3 * H_DIM + h) * 2];      wo1 = w_ih[(size_t)(3 * H_DIM + h) * 2 + 1];
    }

#pragma unroll 4
    for (int it = 0; it < MT / 8; it++) {             // 16 iters, r covers 0..127
        const int r   = (tid >> 5) + it * 8;
        const int row = rowBase + r;
        const int p   = row >> 8;
        const int b   = row & 255;

        float gi = G[r * GP + j]      + bi;
        float gf = G[r * GP + 32 + j] + bf;
        float gg = G[r * GP + 64 + j] + bg;
        float go = G[r * GP + 96 + j] + bo;

        if (LAYER == 0) {
            const float x0 = x_in[(size_t)(b * P_DIM + p) * IN_DIM];
            const float x1 = x_in[(size_t)(b * P_DIM + p) * IN_DIM + 1];
            gi += x0 * wi0 + x1 * wi1;
            gf += x0 * wf0 + x1 * wf1;
            gg += x0 * wg0 + x1 * wg1;
            go += x0 * wo0 + x1 * wo1;
        }

        const float i_s = sigmoidf_fast(gi);
        const float f_s = sigmoidf_fast(gf);
        const float o_s = sigmoidf_fast(go);
        const float g_t = tanhf(gg);

        const size_t cidx = (((size_t)p * 2 + LAYER) * B_DIM + b) * H_DIM + h;
        const float c_new = f_s * c0[cidx] + i_s * g_t;
        const float h_new = o_s * tanhf(c_new);

        d_out[hn_off + cidx] = h_new;
        d_out[cn_off + cidx] = c_new;
        if (LAYER == 0) {
            g_h1[(size_t)row * H_DIM + h] = h_new;
        } else {
            d_out[((size_t)b * P_DIM + p) * H_DIM + h] = h_new;  // out[b,p,h]
        }
    }
}

extern "C" void kernel_launch(void* const* d_in, const int* in_sizes, int n_in,
                              void* d_out, int out_size) {
    const float* x     = (const float*)d_in[0];   // input_traces [B,P,2]
    const float* h0    = (const float*)d_in[1];   // [P,L,B,H]
    const float* c0    = (const float*)d_in[2];   // [P,L,B,H]
    const float* w_ih0 = (const float*)d_in[3];   // [2048,2]
    const float* w_hh0 = (const float*)d_in[4];   // [2048,512]
    const float* b_ih0 = (const float*)d_in[5];
    const float* b_hh0 = (const float*)d_in[6];
    const float* w_ih1 = (const float*)d_in[7];   // [2048,512]
    const float* w_hh1 = (const float*)d_in[8];   // [2048,512]
    const float* b_ih1 = (const float*)d_in[9];
    const float* b_hh1 = (const float*)d_in[10];
    float* out = (float*)d_out;

    const int smem_bytes = 4 * STAGE_F * 4;       // 73728 B
    cudaFuncSetAttribute(lstm_layer_kernel<0>,
                         cudaFuncAttributeMaxDynamicSharedMemorySize, smem_bytes);
    cudaFuncSetAttribute(lstm_layer_kernel<1>,
                         cudaFuncAttributeMaxDynamicSharedMemorySize, smem_bytes);

    dim3 grid(H_DIM / HT, PB / MT);               // (16, 128)
    lstm_layer_kernel<0><<<grid, 256, smem_bytes>>>(x, h0, c0, w_ih0, w_hh0,
                                                    b_ih0, b_hh0, out);
    lstm_layer_kernel<1><<<grid, 256, smem_bytes>>>(nullptr, h0, c0, w_ih1, w_hh1,
                                                    b_ih1, b_hh1, out);
}

// round 8
// speedup vs baseline: 1.1349x; 1.1349x over previous
#include <cuda_runtime.h>
#include <cstdint>

// Problem constants
#define P_DIM 64
#define B_DIM 256
#define H_DIM 512
#define IN_DIM 2
#define PB (P_DIM * B_DIM)      // 16384 fused batch rows

// Tiling
#define MT 128                  // rows per CTA
#define HT 32                   // h-columns per CTA (x4 gates -> 128 N cols)
#define KT 32                   // k per pipeline stage
#define PITCH 36                // smem pitch (floats) -> conflict-free LDSM rows
#define STAGE_F (128 * PITCH)   // floats per (A or B) stage buffer
#define GP 132                  // gate smem pitch

// Layer-0 hidden output scratch (static device global: allocation-free)
__device__ float g_h1[(size_t)PB * H_DIM];

__device__ __forceinline__ void cpa16(unsigned saddr, const float* g) {
    asm volatile("cp.async.cg.shared.global [%0], [%1], 16;\n" :: "r"(saddr), "l"(g));
}

// ldmatrix x4: loads 4 8x8 b16 matrices == 4 8x4 tf32 fragments.
__device__ __forceinline__ void ldsm4(uint32_t* r, uint32_t addr) {
    asm volatile("ldmatrix.sync.aligned.m8n8.x4.shared.b16 {%0,%1,%2,%3}, [%4];"
                 : "=r"(r[0]), "=r"(r[1]), "=r"(r[2]), "=r"(r[3]) : "r"(addr));
}

// tf32 mma fed with raw fp32 bits (HW truncates mantissa to tf32)
__device__ __forceinline__ void mma_tf32(float* c, const uint32_t* a,
                                         uint32_t b0, uint32_t b1) {
    asm volatile(
        "mma.sync.aligned.m16n8k8.row.col.f32.tf32.tf32.f32 "
        "{%0,%1,%2,%3}, {%4,%5,%6,%7}, {%8,%9}, {%0,%1,%2,%3};\n"
        : "+f"(c[0]), "+f"(c[1]), "+f"(c[2]), "+f"(c[3])
        : "r"(a[0]), "r"(a[1]), "r"(a[2]), "r"(a[3]), "r"(b0), "r"(b1));
}

__device__ __forceinline__ float sigmoidf_fast(float x) {
    return 1.0f / (1.0f + __expf(-x));
}

// One LSTM layer, fused GEMM (tf32 mma) + cell.
// LAYER==0: gates = x@w_ih0^T (IN=2, done scalar in epilogue) + h0[:,0]@w_hh0^T + b
// LAYER==1: gates = h1@w_ih1^T + h0[:,1]@w_hh1^T + b  (K=1024 concat)
template <int LAYER>
__global__ void __launch_bounds__(256, 2)
lstm_layer_kernel(const float* __restrict__ x_in,
                  const float* __restrict__ h0,
                  const float* __restrict__ c0,
                  const float* __restrict__ w_ih,
                  const float* __restrict__ w_hh,
                  const float* __restrict__ b_ih,
                  const float* __restrict__ b_hh,
                  float* __restrict__ d_out) {
    extern __shared__ float smem[];

    const int tid  = threadIdx.x;
    const int warp = tid >> 5;
    const int lane = tid & 31;
    const int wm = warp >> 1;          // 0..3 : 32-row slab
    const int wn = warp & 1;           // 0..1 : 64-col half
    const int rowW = wm * 32;
    const int colW = wn * 64;

    const int mTile = blockIdx.y;      // 0..127
    const int hTile = blockIdx.x;      // 0..15
    const int rowBase = mTile * MT;
    const int hBase   = hTile * HT;

    const int p0 = rowBase >> 8;       // row = p*256 + b ; 128-row tile stays in one p
    const int b0 = rowBase & 255;

    // A operand base pointers (rows contiguous with stride H_DIM)
    const float* Ab0;
    const float* Ab1;
    if (LAYER == 0) {
        Ab0 = h0 + ((size_t)(p0 * 2 + 0) * B_DIM + b0) * H_DIM;
        Ab1 = Ab0;  // unused
    } else {
        Ab0 = g_h1 + (size_t)rowBase * H_DIM;
        Ab1 = h0 + ((size_t)(p0 * 2 + 1) * B_DIM + b0) * H_DIM;
    }
    const float* Wb0 = (LAYER == 0) ? w_hh : w_ih;
    const float* Wb1 = w_hh;

    const int KTILES = (LAYER == 0) ? 16 : 32;

    const unsigned smem_u = (unsigned)__cvta_generic_to_shared(smem);

    // -------- stage loader: A tile [128 x KT], B tile [128(gate-blocked n) x KT] --------
    auto load_stage = [&](int kt, int stage) {
        const float* Ab = (LAYER == 0 || kt < 16) ? Ab0 : Ab1;
        const float* Wb = (LAYER == 0 || kt < 16) ? Wb0 : Wb1;
        const int kk = (kt & 15) * KT;
        const unsigned Asd = smem_u + (unsigned)(stage * STAGE_F) * 4u;
        const unsigned Bsd = smem_u + (unsigned)((2 + stage) * STAGE_F) * 4u;
#pragma unroll
        for (int i = 0; i < 4; i++) {
            const int c  = tid + i * 256;       // 0..1023 : 16B chunks
            const int r  = c >> 3;              // 0..127
            const int cc = (c & 7) * 4;         // 0,4,...,28
            cpa16(Asd + (unsigned)(r * PITCH + cc) * 4u,
                  Ab + (size_t)r * H_DIM + kk + cc);
            const int g = r >> 5, j = r & 31;   // gate-blocked weight row
            cpa16(Bsd + (unsigned)(r * PITCH + cc) * 4u,
                  Wb + (size_t)(g * H_DIM + hBase + j) * H_DIM + kk + cc);
        }
        asm volatile("cp.async.commit_group;\n");
    };

    float acc[2][8][4];
#pragma unroll
    for (int mt = 0; mt < 2; mt++)
#pragma unroll
        for (int nt = 0; nt < 8; nt++)
#pragma unroll
            for (int q = 0; q < 4; q++) acc[mt][nt][q] = 0.0f;

    // -------- per-thread LDSM base offsets (bytes) --------
    // x4 matrix id m = lane>>3 ; row-within-matrix l8 = lane&7
    const int m8 = lane >> 3;
    const int l8 = lane & 7;
    // A frag: m0:(rows+0,k+0) m1:(rows+8,k+0) m2:(rows+0,k+4) m3:(rows+8,k+4)
    const uint32_t aoff =
        (uint32_t)(((rowW + (m8 & 1) * 8 + l8) * PITCH + (m8 >> 1) * 4) * 4);
    // B frag pair (nt0=2t): m0:b0(nt0) m1:b1(nt0) m2:b0(nt0+1) m3:b1(nt0+1)
    uint32_t boff[4];
#pragma unroll
    for (int t = 0; t < 4; t++)
        boff[t] = (uint32_t)(((colW + (t * 2 + (m8 >> 1)) * 8 + l8) * PITCH
                              + (m8 & 1) * 4) * 4);

    // -------- mainloop: 2-stage cp.async pipeline --------
    load_stage(0, 0);
    for (int kt = 0; kt < KTILES; kt++) {
        if (kt + 1 < KTILES) {
            load_stage(kt + 1, (kt + 1) & 1);
            asm volatile("cp.async.wait_group 1;\n");
        } else {
            asm volatile("cp.async.wait_group 0;\n");
        }
        __syncthreads();

        const uint32_t As = smem_u + (uint32_t)((kt & 1) * STAGE_F) * 4u;
        const uint32_t Bs = smem_u + (uint32_t)((2 + (kt & 1)) * STAGE_F) * 4u;
#pragma unroll
        for (int k0 = 0; k0 < KT; k0 += 8) {
            uint32_t a0[4], a1[4];
            ldsm4(a0, As + aoff + k0 * 4);
            ldsm4(a1, As + aoff + (uint32_t)(16 * PITCH * 4) + k0 * 4);
#pragma unroll
            for (int t = 0; t < 4; t++) {
                uint32_t b[4];
                ldsm4(b, Bs + boff[t] + k0 * 4);
                mma_tf32(acc[0][2 * t],     a0, b[0], b[1]);
                mma_tf32(acc[1][2 * t],     a1, b[0], b[1]);
                mma_tf32(acc[0][2 * t + 1], a0, b[2], b[3]);
                mma_tf32(acc[1][2 * t + 1], a1, b[2], b[3]);
            }
        }
        __syncthreads();
    }

    // -------- epilogue: gates -> smem (overlay pipeline buffers) --------
    float* G = smem;  // [128][GP], col index = gate*32 + j
#pragma unroll
    for (int mt = 0; mt < 2; mt++) {
#pragma unroll
        for (int nt = 0; nt < 8; nt++) {
            const int r  = rowW + mt * 16 + (lane >> 2);
            const int cC = colW + nt * 8 + 2 * (lane & 3);
            G[r * GP + cC]           = acc[mt][nt][0];
            G[r * GP + cC + 1]       = acc[mt][nt][1];
            G[(r + 8) * GP + cC]     = acc[mt][nt][2];
            G[(r + 8) * GP + cC + 1] = acc[mt][nt][3];
        }
    }
    __syncthreads();

    // -------- LSTM cell + stores --------
    const size_t hn_off = (size_t)PB * H_DIM;                               // out size
    const size_t cn_off = hn_off + (size_t)P_DIM * 2 * B_DIM * H_DIM;       // + hn size

    const int j = tid & 31;           // constant per thread
    const int h = hBase + j;
    // hoist per-thread bias sums and (layer0) input-projection coefficients
    const float bi = b_ih[h]             + b_hh[h];
    const float bf = b_ih[H_DIM + h]     + b_hh[H_DIM + h];
    const float bg = b_ih[2 * H_DIM + h] + b_hh[2 * H_DIM + h];
    const float bo = b_ih[3 * H_DIM + h] + b_hh[3 * H_DIM + h];
    float wi0 = 0.f, wi1 = 0.f, wf0 = 0.f, wf1 = 0.f, wg0 = 0.f, wg1 = 0.f, wo0 = 0.f, wo1 = 0.f;
    if (LAYER == 0) {
        wi0 = w_ih[(size_t)h * 2];                    wi1 = w_ih[(size_t)h * 2 + 1];
        wf0 = w_ih[(size_t)(H_DIM + h) * 2];          wf1 = w_ih[(size_t)(H_DIM + h) * 2 + 1];
        wg0 = w_ih[(size_t)(2 * H_DIM + h) * 2];      wg1 = w_ih[(size_t)(2 * H_DIM + h) * 2 + 1];
        wo0 = w_ih[(size_t)(3 * H_DIM + h) * 2];      wo1 = w_ih[(size_t)(3 * H_DIM + h) * 2 + 1];
    }

#pragma unroll 4
    for (int it = 0; it < MT / 8; it++) {             // 16 iters, r covers 0..127
        const int r   = (tid >> 5) + it * 8;
        const int row = rowBase + r;
        const int p   = row >> 8;
        const int b   = row & 255;

        float gi = G[r * GP + j]      + bi;
        float gf = G[r * GP + 32 + j] + bf;
        float gg = G[r * GP + 64 + j] + bg;
        float go = G[r * GP + 96 + j] + bo;

        if (LAYER == 0) {
            const float x0 = x_in[(size_t)(b * P_DIM + p) * IN_DIM];
            const float x1 = x_in[(size_t)(b * P_DIM + p) * IN_DIM + 1];
            gi += x0 * wi0 + x1 * wi1;
            gf += x0 * wf0 + x1 * wf1;
            gg += x0 * wg0 + x1 * wg1;
            go += x0 * wo0 + x1 * wo1;
        }

        const float i_s = sigmoidf_fast(gi);
        const float f_s = sigmoidf_fast(gf);
        const float o_s = sigmoidf_fast(go);
        const float g_t = tanhf(gg);

        const size_t cidx = (((size_t)p * 2 + LAYER) * B_DIM + b) * H_DIM + h;
        const float c_new = f_s * c0[cidx] + i_s * g_t;
        const float h_new = o_s * tanhf(c_new);

        d_out[hn_off + cidx] = h_new;
        d_out[cn_off + cidx] = c_new;
        if (LAYER == 0) {
            g_h1[(size_t)row * H_DIM + h] = h_new;
        } else {
            d_out[((size_t)b * P_DIM + p) * H_DIM + h] = h_new;  // out[b,p,h]
        }
    }
}

extern "C" void kernel_launch(void* const* d_in, const int* in_sizes, int n_in,
                              void* d_out, int out_size) {
    const float* x     = (const float*)d_in[0];   // input_traces [B,P,2]
    const float* h0    = (const float*)d_in[1];   // [P,L,B,H]
    const float* c0    = (const float*)d_in[2];   // [P,L,B,H]
    const float* w_ih0 = (const float*)d_in[3];   // [2048,2]
    const float* w_hh0 = (const float*)d_in[4];   // [2048,512]
    const float* b_ih0 = (const float*)d_in[5];
    const float* b_hh0 = (const float*)d_in[6];
    const float* w_ih1 = (const float*)d_in[7];   // [2048,512]
    const float* w_hh1 = (const float*)d_in[8];   // [2048,512]
    const float* b_ih1 = (const float*)d_in[9];
    const float* b_hh1 = (const float*)d_in[10];
    float* out = (float*)d_out;

    const int smem_bytes = 4 * STAGE_F * 4;       // 73728 B
    cudaFuncSetAttribute(lstm_layer_kernel<0>,
                         cudaFuncAttributeMaxDynamicSharedMemorySize, smem_bytes);
    cudaFuncSetAttribute(lstm_layer_kernel<1>,
                         cudaFuncAttributeMaxDynamicSharedMemorySize, smem_bytes);

    dim3 grid(H_DIM / HT, PB / MT);               // (16, 128)
    lstm_layer_kernel<0><<<grid, 256, smem_bytes>>>(x, h0, c0, w_ih0, w_hh0,
                                                    b_ih0, b_hh0, out);
    lstm_layer_kernel<1><<<grid, 256, smem_bytes>>>(nullptr, h0, c0, w_ih1, w_hh1,
                                                    b_ih1, b_hh1, out);
}

// round 9
// speedup vs baseline: 1.2943x; 1.1405x over previous
#include <cuda_runtime.h>
#include <cstdint>

// Problem constants
#define P_DIM 64
#define B_DIM 256
#define H_DIM 512
#define IN_DIM 2
#define PB (P_DIM * B_DIM)      // 16384 fused batch rows

// Tiling
#define MT 128                  // rows per CTA
#define HT 32                   // h-columns per CTA (x4 gates -> 128 N cols)
#define KT 32                   // k per pipeline stage
#define NSTAGE 3
#define PITCH 36                // smem pitch (floats) -> conflict-free LDSM rows
#define STAGE_F (128 * PITCH)   // floats per (A or B) stage buffer
#define GP 132                  // gate smem pitch

// Layer-0 hidden output scratch (static device global: allocation-free)
__device__ float g_h1[(size_t)PB * H_DIM];

__device__ __forceinline__ void cpa16(unsigned saddr, const float* g) {
    asm volatile("cp.async.cg.shared.global [%0], [%1], 16;\n" :: "r"(saddr), "l"(g));
}

// ldmatrix x4: loads 4 8x8 b16 matrices == 4 8x4 tf32 fragments.
__device__ __forceinline__ void ldsm4(uint32_t* r, uint32_t addr) {
    asm volatile("ldmatrix.sync.aligned.m8n8.x4.shared.b16 {%0,%1,%2,%3}, [%4];"
                 : "=r"(r[0]), "=r"(r[1]), "=r"(r[2]), "=r"(r[3]) : "r"(addr));
}

// tf32 mma fed with raw fp32 bits (HW truncates mantissa to tf32)
__device__ __forceinline__ void mma_tf32(float* c, const uint32_t* a,
                                         uint32_t b0, uint32_t b1) {
    asm volatile(
        "mma.sync.aligned.m16n8k8.row.col.f32.tf32.tf32.f32 "
        "{%0,%1,%2,%3}, {%4,%5,%6,%7}, {%8,%9}, {%0,%1,%2,%3};\n"
        : "+f"(c[0]), "+f"(c[1]), "+f"(c[2]), "+f"(c[3])
        : "r"(a[0]), "r"(a[1]), "r"(a[2]), "r"(a[3]), "r"(b0), "r"(b1));
}

__device__ __forceinline__ float tanh_fast(float x) {
    float y;
    asm("tanh.approx.f32 %0, %1;" : "=f"(y) : "f"(x));
    return y;
}
__device__ __forceinline__ float sigmoid_fast(float x) {
    return fmaf(tanh_fast(0.5f * x), 0.5f, 0.5f);
}

// One LSTM layer, fused GEMM (tf32 mma) + cell.
// LAYER==0: gates = x@w_ih0^T (IN=2, done scalar in epilogue) + h0[:,0]@w_hh0^T + b
// LAYER==1: gates = h1@w_ih1^T + h0[:,1]@w_hh1^T + b  (K=1024 concat)
template <int LAYER>
__global__ void __launch_bounds__(256, 2)
lstm_layer_kernel(const float* __restrict__ x_in,
                  const float* __restrict__ h0,
                  const float* __restrict__ c0,
                  const float* __restrict__ w_ih,
                  const float* __restrict__ w_hh,
                  const float* __restrict__ b_ih,
                  const float* __restrict__ b_hh,
                  float* __restrict__ d_out) {
    extern __shared__ float smem[];

    const int tid  = threadIdx.x;
    const int warp = tid >> 5;
    const int lane = tid & 31;
    const int wm = warp >> 1;          // 0..3 : 32-row slab
    const int wn = warp & 1;           // 0..1 : 64-col half
    const int rowW = wm * 32;
    const int colW = wn * 64;

    const int mTile = blockIdx.y;      // 0..127
    const int hTile = blockIdx.x;      // 0..15
    const int rowBase = mTile * MT;
    const int hBase   = hTile * HT;

    const int p0 = rowBase >> 8;       // row = p*256 + b ; 128-row tile stays in one p
    const int b0 = rowBase & 255;

    // A operand base pointers (rows contiguous with stride H_DIM)
    const float* Ab0;
    const float* Ab1;
    if (LAYER == 0) {
        Ab0 = h0 + ((size_t)(p0 * 2 + 0) * B_DIM + b0) * H_DIM;
        Ab1 = Ab0;  // unused
    } else {
        Ab0 = g_h1 + (size_t)rowBase * H_DIM;
        Ab1 = h0 + ((size_t)(p0 * 2 + 1) * B_DIM + b0) * H_DIM;
    }
    const float* Wb0 = (LAYER == 0) ? w_hh : w_ih;
    const float* Wb1 = w_hh;

    const int KTILES = (LAYER == 0) ? 16 : 32;

    const unsigned smem_u = (unsigned)__cvta_generic_to_shared(smem);

    // -------- stage loader: A tile [128 x KT], B tile [128(gate-blocked n) x KT] --------
    // stage s layout: A at (2s)*STAGE_F, B at (2s+1)*STAGE_F
    auto load_stage = [&](int kt, int stage) {
        const float* Ab = (LAYER == 0 || kt < 16) ? Ab0 : Ab1;
        const float* Wb = (LAYER == 0 || kt < 16) ? Wb0 : Wb1;
        const int kk = (kt & 15) * KT;
        const unsigned Asd = smem_u + (unsigned)(stage * 2 * STAGE_F) * 4u;
        const unsigned Bsd = Asd + (unsigned)STAGE_F * 4u;
#pragma unroll
        for (int i = 0; i < 4; i++) {
            const int c  = tid + i * 256;       // 0..1023 : 16B chunks
            const int r  = c >> 3;              // 0..127
            const int cc = (c & 7) * 4;         // 0,4,...,28
            cpa16(Asd + (unsigned)(r * PITCH + cc) * 4u,
                  Ab + (size_t)r * H_DIM + kk + cc);
            const int g = r >> 5, j = r & 31;   // gate-blocked weight row
            cpa16(Bsd + (unsigned)(r * PITCH + cc) * 4u,
                  Wb + (size_t)(g * H_DIM + hBase + j) * H_DIM + kk + cc);
        }
        asm volatile("cp.async.commit_group;\n");
    };

    float acc[2][8][4];
#pragma unroll
    for (int mt = 0; mt < 2; mt++)
#pragma unroll
        for (int nt = 0; nt < 8; nt++)
#pragma unroll
            for (int q = 0; q < 4; q++) acc[mt][nt][q] = 0.0f;

    // -------- per-thread LDSM base offsets (bytes) --------
    const int m8 = lane >> 3;
    const int l8 = lane & 7;
    // A frag: m0:(rows+0,k+0) m1:(rows+8,k+0) m2:(rows+0,k+4) m3:(rows+8,k+4)
    const uint32_t aoff =
        (uint32_t)(((rowW + (m8 & 1) * 8 + l8) * PITCH + (m8 >> 1) * 4) * 4);
    // B frag pair (nt0=2t): m0:b0(nt0) m1:b1(nt0) m2:b0(nt0+1) m3:b1(nt0+1)
    uint32_t boff[4];
#pragma unroll
    for (int t = 0; t < 4; t++)
        boff[t] = (uint32_t)(((colW + (t * 2 + (m8 >> 1)) * 8 + l8) * PITCH
                              + (m8 & 1) * 4) * 4);

    // -------- mainloop: 3-stage cp.async pipeline, one sync per k-tile --------
    load_stage(0, 0);
    load_stage(1, 1);
    asm volatile("cp.async.wait_group 1;\n");   // stage 0 ready
    __syncthreads();

    int s = 0;                                  // = kt % 3
    for (int kt = 0; kt < KTILES; kt++) {
        // prefetch stage kt+2 (overwrites stage (kt-1)%3; safe: end-of-(kt-1) sync passed)
        if (kt + 2 < KTILES) {
            int s2 = s + 2; if (s2 >= 3) s2 -= 3;
            load_stage(kt + 2, s2);
        }

        const uint32_t As = smem_u + (uint32_t)(s * 2 * STAGE_F) * 4u;
        const uint32_t Bs = As + (uint32_t)STAGE_F * 4u;
#pragma unroll
        for (int k0 = 0; k0 < KT; k0 += 8) {
            uint32_t a0[4], a1[4];
            ldsm4(a0, As + aoff + k0 * 4);
            ldsm4(a1, As + aoff + (uint32_t)(16 * PITCH * 4) + k0 * 4);
#pragma unroll
            for (int t = 0; t < 4; t++) {
                uint32_t b[4];
                ldsm4(b, Bs + boff[t] + k0 * 4);
                mma_tf32(acc[0][2 * t],     a0, b[0], b[1]);
                mma_tf32(acc[1][2 * t],     a1, b[0], b[1]);
                mma_tf32(acc[0][2 * t + 1], a0, b[2], b[3]);
                mma_tf32(acc[1][2 * t + 1], a1, b[2], b[3]);
            }
        }

        // end-of-iter: make stage kt+1 ready & visible for next iteration
        if (kt + 1 < KTILES) {
            if (kt + 2 < KTILES) { asm volatile("cp.async.wait_group 1;\n"); }
            else                 { asm volatile("cp.async.wait_group 0;\n"); }
            __syncthreads();
        }
        if (++s == 3) s = 0;
    }
    __syncthreads();   // protect stage smem before G overlay writes

    // -------- epilogue: gates -> smem (overlay pipeline buffers) --------
    float* G = smem;  // [128][GP], col index = gate*32 + j
#pragma unroll
    for (int mt = 0; mt < 2; mt++) {
#pragma unroll
        for (int nt = 0; nt < 8; nt++) {
            const int r  = rowW + mt * 16 + (lane >> 2);
            const int cC = colW + nt * 8 + 2 * (lane & 3);
            G[r * GP + cC]           = acc[mt][nt][0];
            G[r * GP + cC + 1]       = acc[mt][nt][1];
            G[(r + 8) * GP + cC]     = acc[mt][nt][2];
            G[(r + 8) * GP + cC + 1] = acc[mt][nt][3];
        }
    }
    __syncthreads();

    // -------- LSTM cell + stores --------
    const size_t hn_off = (size_t)PB * H_DIM;                               // out size
    const size_t cn_off = hn_off + (size_t)P_DIM * 2 * B_DIM * H_DIM;       // + hn size

    const int j = tid & 31;           // constant per thread
    const int h = hBase + j;
    const float bi = b_ih[h]             + b_hh[h];
    const float bf = b_ih[H_DIM + h]     + b_hh[H_DIM + h];
    const float bg = b_ih[2 * H_DIM + h] + b_hh[2 * H_DIM + h];
    const float bo = b_ih[3 * H_DIM + h] + b_hh[3 * H_DIM + h];
    float wi0 = 0.f, wi1 = 0.f, wf0 = 0.f, wf1 = 0.f, wg0 = 0.f, wg1 = 0.f, wo0 = 0.f, wo1 = 0.f;
    if (LAYER == 0) {
        wi0 = w_ih[(size_t)h * 2];                    wi1 = w_ih[(size_t)h * 2 + 1];
        wf0 = w_ih[(size_t)(H_DIM + h) * 2];          wf1 = w_ih[(size_t)(H_DIM + h) * 2 + 1];
        wg0 = w_ih[(size_t)(2 * H_DIM + h) * 2];      wg1 = w_ih[(size_t)(2 * H_DIM + h) * 2 + 1];
        wo0 = w_ih[(size_t)(3 * H_DIM + h) * 2];      wo1 = w_ih[(size_t)(3 * H_DIM + h) * 2 + 1];
    }

#pragma unroll 4
    for (int it = 0; it < MT / 8; it++) {             // 16 iters, r covers 0..127
        const int r   = (tid >> 5) + it * 8;
        const int row = rowBase + r;
        const int p   = row >> 8;
        const int b   = row & 255;

        float gi = G[r * GP + j]      + bi;
        float gf = G[r * GP + 32 + j] + bf;
        float gg = G[r * GP + 64 + j] + bg;
        float go = G[r * GP + 96 + j] + bo;

        if (LAYER == 0) {
            const float x0 = x_in[(size_t)(b * P_DIM + p) * IN_DIM];
            const float x1 = x_in[(size_t)(b * P_DIM + p) * IN_DIM + 1];
            gi += x0 * wi0 + x1 * wi1;
            gf += x0 * wf0 + x1 * wf1;
            gg += x0 * wg0 + x1 * wg1;
            go += x0 * wo0 + x1 * wo1;
        }

        const float i_s = sigmoid_fast(gi);
        const float f_s = sigmoid_fast(gf);
        const float o_s = sigmoid_fast(go);
        const float g_t = tanh_fast(gg);

        const size_t cidx = (((size_t)p * 2 + LAYER) * B_DIM + b) * H_DIM + h;
        const float c_new = f_s * c0[cidx] + i_s * g_t;
        const float h_new = o_s * tanh_fast(c_new);

        d_out[hn_off + cidx] = h_new;
        d_out[cn_off + cidx] = c_new;
        if (LAYER == 0) {
            g_h1[(size_t)row * H_DIM + h] = h_new;
        } else {
            d_out[((size_t)b * P_DIM + p) * H_DIM + h] = h_new;  // out[b,p,h]
        }
    }
}

extern "C" void kernel_launch(void* const* d_in, const int* in_sizes, int n_in,
                              void* d_out, int out_size) {
    const float* x     = (const float*)d_in[0];   // input_traces [B,P,2]
    const float* h0    = (const float*)d_in[1];   // [P,L,B,H]
    const float* c0    = (const float*)d_in[2];   // [P,L,B,H]
    const float* w_ih0 = (const float*)d_in[3];   // [2048,2]
    const float* w_hh0 = (const float*)d_in[4];   // [2048,512]
    const float* b_ih0 = (const float*)d_in[5];
    const float* b_hh0 = (const float*)d_in[6];
    const float* w_ih1 = (const float*)d_in[7];   // [2048,512]
    const float* w_hh1 = (const float*)d_in[8];   // [2048,512]
    const float* b_ih1 = (const float*)d_in[9];
    const float* b_hh1 = (const float*)d_in[10];
    float* out = (float*)d_out;

    const int smem_bytes = 2 * NSTAGE * STAGE_F * 4;   // 110592 B
    cudaFuncSetAttribute(lstm_layer_kernel<0>,
                         cudaFuncAttributeMaxDynamicSharedMemorySize, smem_bytes);
    cudaFuncSetAttribute(lstm_layer_kernel<1>,
                         cudaFuncAttributeMaxDynamicSharedMemorySize, smem_bytes);

    dim3 grid(H_DIM / HT, PB / MT);               // (16, 128)
    lstm_layer_kernel<0><<<grid, 256, smem_bytes>>>(x, h0, c0, w_ih0, w_hh0,
                                                    b_ih0, b_hh0, out);
    lstm_layer_kernel<1><<<grid, 256, smem_bytes>>>(nullptr, h0, c0, w_ih1, w_hh1,
                                                    b_ih1, b_hh1, out);
}